// round 1
// baseline (speedup 1.0000x reference)
#include <cuda_runtime.h>

#define D_DIM   128
#define K_CODES 1024
#define BPX     128            // pixels per block
#define BC      128            // codes per chunk
#define NCHUNK  (K_CODES / BC) // 8
#define TPB     256
#define SMEM_BYTES ((D_DIM * BPX + 2 * D_DIM * BC) * 4)  // 196608

// Scratch (no dynamic allocation allowed): transposed codebook + ||e||^2
__device__ float g_Et[D_DIM * K_CODES];  // Et[d][k]
__device__ float g_e2[K_CODES];

typedef unsigned long long ull;

__device__ __forceinline__ ull dup2(float v) {
    ull r; asm("mov.b64 %0, {%1, %1};" : "=l"(r) : "f"(v)); return r;
}
__device__ __forceinline__ ull fma2(ull a, ull b, ull c) {
    ull d; asm("fma.rn.f32x2 %0, %1, %2, %3;" : "=l"(d) : "l"(a), "l"(b), "l"(c)); return d;
}
__device__ __forceinline__ void unpack2(ull v, float& a, float& b) {
    asm("mov.b64 {%0, %1}, %2;" : "=f"(a), "=f"(b) : "l"(v));
}
__device__ __forceinline__ void cp16(void* s, const void* g) {
    unsigned sa = (unsigned)__cvta_generic_to_shared(s);
    asm volatile("cp.async.cg.shared.global [%0], [%1], 16;" :: "r"(sa), "l"(g));
}

// Transpose codebook -> Et[d][k], and e2[k] = sum_d cb[k][d]^2 (fp32, sequential).
__global__ void prep_kernel(const float* __restrict__ cb) {
    int i = blockIdx.x * blockDim.x + threadIdx.x;
    int nt = gridDim.x * blockDim.x;
    for (int idx = i; idx < D_DIM * K_CODES; idx += nt) {
        int k = idx >> 7, d = idx & 127;
        g_Et[d * K_CODES + k] = cb[idx];
    }
    if (i < K_CODES) {
        const float* row = cb + i * D_DIM;
        float s = 0.f;
        for (int d = 0; d < D_DIM; d++) s = __fadd_rn(s, __fmul_rn(row[d], row[d]));
        g_e2[i] = s;
    }
}

__global__ __launch_bounds__(TPB, 1) void vq_main(const float* __restrict__ lat,
                                                  float* __restrict__ out) {
    extern __shared__ float smem[];
    float* Xs  = smem;                    // [d][px]  64 KB
    float* Es0 = smem + D_DIM * BPX;      // chunk buf 0, [d][c] 64 KB
    float* Es1 = Es0 + D_DIM * BC;        // chunk buf 1, 64 KB

    __shared__ float x2s[BPX];
    __shared__ int   bests[BPX];

    const int tid = threadIdx.x;
    const int tx  = tid & 15;     // code group
    const int ty  = tid >> 4;     // pixel group
    const int p0  = ty * 8;
    const int c0  = tx * 8;

    const int gp  = blockIdx.x * BPX;     // global pixel index
    const int b   = gp >> 12;             // / 4096
    const int hw0 = gp & 4095;
    const float* latbase = lat + (size_t)b * D_DIM * 4096 + hw0;

    // Issue chunk-0 E load (async) before anything else.
    for (int i = tid; i < D_DIM * BC / 4; i += TPB) {
        int d = i >> 5, c4 = (i & 31) << 2;
        cp16(&Es0[d * BC + c4], &g_Et[d * K_CODES + c4]);
    }
    asm volatile("cp.async.commit_group;");

    // Load X tile (coalesced: per-d, 128 contiguous pixels).
    for (int i = tid; i < D_DIM * BPX / 4; i += TPB) {
        int d = i >> 5, c4 = (i & 31) << 2;
        *(float4*)&Xs[d * BPX + c4] = *(const float4*)&latbase[(size_t)d * 4096 + c4];
    }
    __syncthreads();

    // x2 per pixel (fp32 sequential sum; exact bit value provably irrelevant
    // to the argmin up to a uniform-shift, only the formula structure matters).
    if (tid < BPX) {
        float s = 0.f;
        for (int d = 0; d < D_DIM; d++) {
            float v = Xs[d * BPX + tid];
            s = __fadd_rn(s, __fmul_rn(v, v));
        }
        x2s[tid] = s;
    }

    asm volatile("cp.async.wait_group 0;" ::: "memory");
    __syncthreads();

    float bestV[8];
    int   bestI[8];
    #pragma unroll
    for (int p = 0; p < 8; p++) { bestV[p] = 3.4e38f; bestI[p] = 0; }

    for (int ch = 0; ch < NCHUNK; ch++) {
        float* Eb = (ch & 1) ? Es1 : Es0;

        // Prefetch next chunk into the other buffer (overlaps with compute).
        if (ch + 1 < NCHUNK) {
            float* nb = ((ch + 1) & 1) ? Es1 : Es0;
            for (int i = tid; i < D_DIM * BC / 4; i += TPB) {
                int d = i >> 5, c4 = (i & 31) << 2;
                cp16(&nb[d * BC + c4], &g_Et[d * K_CODES + (ch + 1) * BC + c4]);
            }
            asm volatile("cp.async.commit_group;");
        }

        // ---- GEMM microtile: 8 px x 8 codes, codes packed pairwise (f32x2) ----
        ull acc[8][4];
        #pragma unroll
        for (int p = 0; p < 8; p++) {
            acc[p][0] = 0ull; acc[p][1] = 0ull; acc[p][2] = 0ull; acc[p][3] = 0ull;
        }

        const float* Ep = Eb + c0;
        const float* Xp = Xs + p0;
        #pragma unroll 4
        for (int k = 0; k < D_DIM; k++) {
            ulonglong2 ea  = *(const ulonglong2*)(Ep + k * BC);
            ulonglong2 ebb = *(const ulonglong2*)(Ep + k * BC + 4);
            float4 xa = *(const float4*)(Xp + k * BPX);
            float4 xb = *(const float4*)(Xp + k * BPX + 4);
            ull e0 = ea.x, e1 = ea.y, e2p = ebb.x, e3 = ebb.y;
            float xs8[8] = {xa.x, xa.y, xa.z, xa.w, xb.x, xb.y, xb.z, xb.w};
            #pragma unroll
            for (int p = 0; p < 8; p++) {
                ull xd = dup2(xs8[p]);
                acc[p][0] = fma2(xd, e0,  acc[p][0]);
                acc[p][1] = fma2(xd, e1,  acc[p][1]);
                acc[p][2] = fma2(xd, e2p, acc[p][2]);
                acc[p][3] = fma2(xd, e3,  acc[p][3]);
            }
        }

        // ---- Epilogue: scores with exact reference rounding, running argmin ----
        const int cg0 = ch * BC + c0;
        float e2v[8];
        #pragma unroll
        for (int j = 0; j < 8; j++) e2v[j] = __ldg(&g_e2[cg0 + j]);

        #pragma unroll
        for (int p = 0; p < 8; p++) {
            float x2 = x2s[p0 + p];
            float v = 3.4e38f; int idx = 0;
            #pragma unroll
            for (int j = 0; j < 4; j++) {
                float d0, d1;
                unpack2(acc[p][j], d0, d1);
                // d2 = fl(fl(x2 - 2*dot) + e2)  — replicates reference fp32 formula
                float s0 = __fadd_rn(__fsub_rn(x2, __fmul_rn(2.0f, d0)), e2v[2 * j]);
                float s1 = __fadd_rn(__fsub_rn(x2, __fmul_rn(2.0f, d1)), e2v[2 * j + 1]);
                if (s0 < v) { v = s0; idx = cg0 + 2 * j; }
                if (s1 < v) { v = s1; idx = cg0 + 2 * j + 1; }
            }
            // Reduce over the 16 lanes sharing these pixels (lowest-index ties).
            #pragma unroll
            for (int off = 1; off < 16; off <<= 1) {
                float ov = __shfl_xor_sync(0xffffffffu, v, off);
                int   oi = __shfl_xor_sync(0xffffffffu, idx, off);
                if (ov < v || (ov == v && oi < idx)) { v = ov; idx = oi; }
            }
            if (v < bestV[p]) { bestV[p] = v; bestI[p] = idx; }  // earlier chunk wins ties
        }

        if (ch + 1 < NCHUNK)
            asm volatile("cp.async.wait_group 0;" ::: "memory");
        __syncthreads();
    }

    if (tx == 0) {
        #pragma unroll
        for (int p = 0; p < 8; p++) bests[p0 + p] = bestI[p];
    }
    __syncthreads();

    // Gather codebook rows and write channel-first output (coalesced stores).
    float* outbase = out + (size_t)b * D_DIM * 4096 + hw0;
    for (int i = tid; i < D_DIM * BPX; i += TPB) {
        int d = i >> 7, px = i & 127;
        outbase[(size_t)d * 4096 + px] = __ldg(&g_Et[d * K_CODES + bests[px]]);
    }
}

extern "C" void kernel_launch(void* const* d_in, const int* in_sizes, int n_in,
                              void* d_out, int out_size) {
    const float* lat = (const float*)d_in[0];
    const float* cb  = (const float*)d_in[1];
    float* out = (float*)d_out;

    cudaFuncSetAttribute(vq_main, cudaFuncAttributeMaxDynamicSharedMemorySize, SMEM_BYTES);

    prep_kernel<<<256, 256>>>(cb);
    vq_main<<<512, TPB, SMEM_BYTES>>>(lat, out);
}

// round 2
// speedup vs baseline: 1.0029x; 1.0029x over previous
#include <cuda_runtime.h>

#define D_DIM   128
#define K_CODES 1024
#define BPX     128            // pixels per block
#define BC      128            // codes per chunk
#define NCHUNK  (K_CODES / BC) // 8
#define TPB     256
#define SMEM_BYTES ((D_DIM * BPX + 2 * D_DIM * BC) * 4)  // 196608

// Scratch (no dynamic allocation allowed): transposed codebook + ||e||^2
__device__ float g_Et[D_DIM * K_CODES];  // Et[d][k]
__device__ float g_e2[K_CODES];

typedef unsigned long long ull;

__device__ __forceinline__ ull dup2(float v) {
    ull r; asm("mov.b64 %0, {%1, %1};" : "=l"(r) : "f"(v)); return r;
}
__device__ __forceinline__ ull fma2(ull a, ull b, ull c) {
    ull d; asm("fma.rn.f32x2 %0, %1, %2, %3;" : "=l"(d) : "l"(a), "l"(b), "l"(c)); return d;
}
__device__ __forceinline__ void unpack2(ull v, float& a, float& b) {
    asm("mov.b64 {%0, %1}, %2;" : "=f"(a), "=f"(b) : "l"(v));
}
__device__ __forceinline__ void cp16(void* s, const void* g) {
    unsigned sa = (unsigned)__cvta_generic_to_shared(s);
    asm volatile("cp.async.cg.shared.global [%0], [%1], 16;" :: "r"(sa), "l"(g));
}

// Transpose codebook -> Et[d][k], and e2[k] = sum_d cb[k][d]^2 (fp32, sequential).
__global__ void prep_kernel(const float* __restrict__ cb) {
    int i = blockIdx.x * blockDim.x + threadIdx.x;
    int nt = gridDim.x * blockDim.x;
    for (int idx = i; idx < D_DIM * K_CODES; idx += nt) {
        int k = idx >> 7, d = idx & 127;
        g_Et[d * K_CODES + k] = cb[idx];
    }
    if (i < K_CODES) {
        const float* row = cb + i * D_DIM;
        float s = 0.f;
        for (int d = 0; d < D_DIM; d++) s = __fadd_rn(s, __fmul_rn(row[d], row[d]));
        g_e2[i] = s;
    }
}

__global__ __launch_bounds__(TPB, 1) void vq_main(const float* __restrict__ lat,
                                                  float* __restrict__ out) {
    extern __shared__ float smem[];
    float* Xs  = smem;                    // [d][px]  64 KB
    float* Es0 = smem + D_DIM * BPX;      // chunk buf 0, [d][c] 64 KB
    float* Es1 = Es0 + D_DIM * BC;        // chunk buf 1, 64 KB

    __shared__ float x2s[BPX];
    __shared__ int   bests[BPX];

    const int tid = threadIdx.x;
    const int tx  = tid & 15;     // code group
    const int ty  = tid >> 4;     // pixel group
    const int p0  = ty * 8;
    const int c0  = tx * 8;

    const int gp  = blockIdx.x * BPX;     // global pixel index
    const int b   = gp >> 12;             // / 4096
    const int hw0 = gp & 4095;
    const float* latbase = lat + (size_t)b * D_DIM * 4096 + hw0;

    // Issue chunk-0 E load (async) before anything else.
    for (int i = tid; i < D_DIM * BC / 4; i += TPB) {
        int d = i >> 5, c4 = (i & 31) << 2;
        cp16(&Es0[d * BC + c4], &g_Et[d * K_CODES + c4]);
    }
    asm volatile("cp.async.commit_group;");

    // Load X tile (coalesced: per-d, 128 contiguous pixels).
    for (int i = tid; i < D_DIM * BPX / 4; i += TPB) {
        int d = i >> 5, c4 = (i & 31) << 2;
        *(float4*)&Xs[d * BPX + c4] = *(const float4*)&latbase[(size_t)d * 4096 + c4];
    }
    __syncthreads();

    // x2 per pixel (fp32 sequential sum; exact bit value provably irrelevant
    // to the argmin up to a uniform-shift, only the formula structure matters).
    if (tid < BPX) {
        float s = 0.f;
        for (int d = 0; d < D_DIM; d++) {
            float v = Xs[d * BPX + tid];
            s = __fadd_rn(s, __fmul_rn(v, v));
        }
        x2s[tid] = s;
    }

    asm volatile("cp.async.wait_group 0;" ::: "memory");
    __syncthreads();

    float bestV[8];
    int   bestI[8];
    #pragma unroll
    for (int p = 0; p < 8; p++) { bestV[p] = 3.4e38f; bestI[p] = 0; }

    for (int ch = 0; ch < NCHUNK; ch++) {
        float* Eb = (ch & 1) ? Es1 : Es0;

        // Prefetch next chunk into the other buffer (overlaps with compute).
        if (ch + 1 < NCHUNK) {
            float* nb = ((ch + 1) & 1) ? Es1 : Es0;
            for (int i = tid; i < D_DIM * BC / 4; i += TPB) {
                int d = i >> 5, c4 = (i & 31) << 2;
                cp16(&nb[d * BC + c4], &g_Et[d * K_CODES + (ch + 1) * BC + c4]);
            }
            asm volatile("cp.async.commit_group;");
        }

        // ---- GEMM microtile: 8 px x 8 codes, codes packed pairwise (f32x2) ----
        ull acc[8][4];
        #pragma unroll
        for (int p = 0; p < 8; p++) {
            acc[p][0] = 0ull; acc[p][1] = 0ull; acc[p][2] = 0ull; acc[p][3] = 0ull;
        }

        const float* Ep = Eb + c0;
        const float* Xp = Xs + p0;
        #pragma unroll 4
        for (int k = 0; k < D_DIM; k++) {
            ulonglong2 ea  = *(const ulonglong2*)(Ep + k * BC);
            ulonglong2 ebb = *(const ulonglong2*)(Ep + k * BC + 4);
            float4 xa = *(const float4*)(Xp + k * BPX);
            float4 xb = *(const float4*)(Xp + k * BPX + 4);
            ull e0 = ea.x, e1 = ea.y, e2p = ebb.x, e3 = ebb.y;
            float xs8[8] = {xa.x, xa.y, xa.z, xa.w, xb.x, xb.y, xb.z, xb.w};
            #pragma unroll
            for (int p = 0; p < 8; p++) {
                ull xd = dup2(xs8[p]);
                acc[p][0] = fma2(xd, e0,  acc[p][0]);
                acc[p][1] = fma2(xd, e1,  acc[p][1]);
                acc[p][2] = fma2(xd, e2p, acc[p][2]);
                acc[p][3] = fma2(xd, e3,  acc[p][3]);
            }
        }

        // ---- Epilogue: scores with exact reference rounding, running argmin ----
        const int cg0 = ch * BC + c0;
        float e2v[8];
        #pragma unroll
        for (int j = 0; j < 8; j++) e2v[j] = __ldg(&g_e2[cg0 + j]);

        #pragma unroll
        for (int p = 0; p < 8; p++) {
            float x2 = x2s[p0 + p];
            float v = 3.4e38f; int idx = 0;
            #pragma unroll
            for (int j = 0; j < 4; j++) {
                float d0, d1;
                unpack2(acc[p][j], d0, d1);
                // d2 = fl(fl(x2 - 2*dot) + e2)  — replicates reference fp32 formula
                float s0 = __fadd_rn(__fsub_rn(x2, __fmul_rn(2.0f, d0)), e2v[2 * j]);
                float s1 = __fadd_rn(__fsub_rn(x2, __fmul_rn(2.0f, d1)), e2v[2 * j + 1]);
                if (s0 < v) { v = s0; idx = cg0 + 2 * j; }
                if (s1 < v) { v = s1; idx = cg0 + 2 * j + 1; }
            }
            // Reduce over the 16 lanes sharing these pixels (lowest-index ties).
            #pragma unroll
            for (int off = 1; off < 16; off <<= 1) {
                float ov = __shfl_xor_sync(0xffffffffu, v, off);
                int   oi = __shfl_xor_sync(0xffffffffu, idx, off);
                if (ov < v || (ov == v && oi < idx)) { v = ov; idx = oi; }
            }
            if (v < bestV[p]) { bestV[p] = v; bestI[p] = idx; }  // earlier chunk wins ties
        }

        if (ch + 1 < NCHUNK)
            asm volatile("cp.async.wait_group 0;" ::: "memory");
        __syncthreads();
    }

    if (tx == 0) {
        #pragma unroll
        for (int p = 0; p < 8; p++) bests[p0 + p] = bestI[p];
    }
    __syncthreads();

    // Gather codebook rows and write channel-first output (coalesced stores).
    float* outbase = out + (size_t)b * D_DIM * 4096 + hw0;
    for (int i = tid; i < D_DIM * BPX; i += TPB) {
        int d = i >> 7, px = i & 127;
        outbase[(size_t)d * 4096 + px] = __ldg(&g_Et[d * K_CODES + bests[px]]);
    }
}

extern "C" void kernel_launch(void* const* d_in, const int* in_sizes, int n_in,
                              void* d_out, int out_size) {
    const float* lat = (const float*)d_in[0];
    const float* cb  = (const float*)d_in[1];
    float* out = (float*)d_out;

    cudaFuncSetAttribute(vq_main, cudaFuncAttributeMaxDynamicSharedMemorySize, SMEM_BYTES);

    prep_kernel<<<256, 256>>>(cb);
    vq_main<<<512, TPB, SMEM_BYTES>>>(lat, out);
}

// round 6
// speedup vs baseline: 1.1586x; 1.1553x over previous
#include <cuda_runtime.h>
#include <cstdint>

#define D_DIM   128
#define K_CODES 1024
#define BPX     128            // pixels per block
#define BC      128            // codes per chunk
#define NCHUNK  (K_CODES / BC) // 8
#define TPB     256
#define XSTR    136            // padded row stride (floats) -> conflict-free frag loads
#define ESTR    136
#define SMEM_DYN ((XSTR * D_DIM + 2 * ESTR * D_DIM) * 4)   // 208896 B

// Scratch (no dynamic allocation allowed): transposed codebook + ||e||^2
__device__ float g_Et[D_DIM * K_CODES];  // Et[d][k]
__device__ float g_e2[K_CODES];

__device__ __forceinline__ unsigned tf32hi(float v) {
    unsigned u; asm("cvt.rna.tf32.f32 %0, %1;" : "=r"(u) : "f"(v)); return u;
}
__device__ __forceinline__ void split_tf32(float v, unsigned& hi, unsigned& lo) {
    hi = tf32hi(v);
    lo = tf32hi(v - __uint_as_float(hi));
}
__device__ __forceinline__ void mma8(float* d, const unsigned* a, unsigned b0, unsigned b1) {
    asm volatile(
        "mma.sync.aligned.m16n8k8.row.col.f32.tf32.tf32.f32 "
        "{%0,%1,%2,%3}, {%4,%5,%6,%7}, {%8,%9}, {%0,%1,%2,%3};"
        : "+f"(d[0]), "+f"(d[1]), "+f"(d[2]), "+f"(d[3])
        : "r"(a[0]), "r"(a[1]), "r"(a[2]), "r"(a[3]), "r"(b0), "r"(b1));
}
__device__ __forceinline__ void cp16(void* s, const void* g) {
    unsigned sa = (unsigned)__cvta_generic_to_shared(s);
    asm volatile("cp.async.cg.shared.global [%0], [%1], 16;" :: "r"(sa), "l"(g));
}

// Transpose codebook -> Et[d][k], and e2[k] = sum_d cb[k][d]^2 (fp32, sequential).
__global__ void prep_kernel(const float* __restrict__ cb) {
    int i = blockIdx.x * blockDim.x + threadIdx.x;
    int nt = gridDim.x * blockDim.x;
    for (int idx = i; idx < D_DIM * K_CODES; idx += nt) {
        int k = idx >> 7, d = idx & 127;
        g_Et[d * K_CODES + k] = cb[idx];
    }
    for (int k = i; k < K_CODES; k += nt) {
        const float* row = cb + k * D_DIM;
        float s = 0.f;
        for (int d = 0; d < D_DIM; d++) s = __fadd_rn(s, __fmul_rn(row[d], row[d]));
        g_e2[k] = s;
    }
}

__global__ __launch_bounds__(TPB, 1) void vq_main(const float* __restrict__ lat,
                                                  float* __restrict__ out) {
    extern __shared__ float smem[];
    float* Xs  = smem;                       // [k=d][px], stride 136
    float* Es0 = Xs + XSTR * D_DIM;          // chunk buf 0: [k=d][c], stride 136
    float* Es1 = Es0 + ESTR * D_DIM;         // chunk buf 1

    __shared__ float x2s[BPX];
    __shared__ float e2s[K_CODES];
    __shared__ float bVs[BPX];
    __shared__ int   bIs[BPX];

    const int tid  = threadIdx.x;
    const int wid  = tid >> 5;
    const int lane = tid & 31;
    const int g    = lane >> 2;      // group id (row within fragment)
    const int t4   = lane & 3;       // thread-in-group (k / col pairing)
    const int w_m  = wid >> 1;       // 4 m-warps
    const int w_n  = wid & 1;        // 2 n-warps
    const int p0   = w_m * 32;       // warp pixel base
    const int c0   = w_n * 64;       // warp code base within chunk

    const int gp  = blockIdx.x * BPX;
    const int b   = gp >> 12;
    const int hw0 = gp & 4095;
    const float* latbase = lat + (size_t)b * D_DIM * 4096 + hw0;

    // Issue chunk-0 E load (async) before anything else.
    for (int i = tid; i < D_DIM * 32; i += TPB) {
        int d = i >> 5, c4 = (i & 31) << 2;
        cp16(&Es0[d * ESTR + c4], &g_Et[d * K_CODES + c4]);
    }
    asm volatile("cp.async.commit_group;");

    // Load X tile (coalesced: per-d, 128 contiguous pixels) into padded rows.
    for (int i = tid; i < D_DIM * 32; i += TPB) {
        int d = i >> 5, c4 = (i & 31) << 2;
        *(float4*)&Xs[d * XSTR + c4] = *(const float4*)&latbase[(size_t)d * 4096 + c4];
    }
    for (int i = tid; i < K_CODES; i += TPB) e2s[i] = g_e2[i];
    __syncthreads();

    // x2 per pixel (same sequential-d fp32 sum as the passing R1 kernel)
    if (tid < BPX) {
        float s = 0.f;
        for (int d = 0; d < D_DIM; d++) {
            float v = Xs[d * XSTR + tid];
            s = __fadd_rn(s, __fmul_rn(v, v));
        }
        x2s[tid] = s;
    }
    asm volatile("cp.async.wait_group 0;" ::: "memory");
    __syncthreads();

    // Per-thread row slots: slot = m*2+rr -> pixel row p0 + m*16 + rr*8 + g
    float x2r[4], bv[4];
    int   bi[4];
    #pragma unroll
    for (int s = 0; s < 4; s++) {
        x2r[s] = x2s[p0 + (s >> 1) * 16 + (s & 1) * 8 + g];
        bv[s] = 3.4e38f; bi[s] = 0;
    }

    for (int ch = 0; ch < NCHUNK; ch++) {
        float* Eb = (ch & 1) ? Es1 : Es0;

        if (ch + 1 < NCHUNK) {   // prefetch next chunk into the other buffer
            float* nb = ((ch + 1) & 1) ? Es1 : Es0;
            for (int i = tid; i < D_DIM * 32; i += TPB) {
                int d = i >> 5, c4 = (i & 31) << 2;
                cp16(&nb[d * ESTR + c4], &g_Et[d * K_CODES + (ch + 1) * BC + c4]);
            }
            asm volatile("cp.async.commit_group;");
        }

        // ---- warp-tiled 3-pass tf32 MMA: 32px x 64codes per warp ----
        float D[2][8][4];
        #pragma unroll
        for (int m = 0; m < 2; m++)
            #pragma unroll
            for (int n = 0; n < 8; n++)
                #pragma unroll
                for (int q = 0; q < 4; q++) D[m][n][q] = 0.f;

        #pragma unroll 4
        for (int kb = 0; kb < D_DIM; kb += 8) {
            const float* Xk0 = Xs + (kb + t4) * XSTR + p0 + g;
            const float* Xk4 = Xk0 + 4 * XSTR;
            unsigned ahi[2][4], alo[2][4];
            #pragma unroll
            for (int m = 0; m < 2; m++) {
                split_tf32(Xk0[m * 16],     ahi[m][0], alo[m][0]);
                split_tf32(Xk0[m * 16 + 8], ahi[m][1], alo[m][1]);
                split_tf32(Xk4[m * 16],     ahi[m][2], alo[m][2]);
                split_tf32(Xk4[m * 16 + 8], ahi[m][3], alo[m][3]);
            }
            const float* Ek0 = Eb + (kb + t4) * ESTR + c0 + g;
            const float* Ek4 = Ek0 + 4 * ESTR;
            #pragma unroll
            for (int n = 0; n < 8; n++) {
                unsigned bh0, bl0, bh1, bl1;
                split_tf32(Ek0[n * 8], bh0, bl0);
                split_tf32(Ek4[n * 8], bh1, bl1);
                #pragma unroll
                for (int m = 0; m < 2; m++) {
                    mma8(D[m][n], ahi[m], bh0, bh1);   // hi*hi
                    mma8(D[m][n], alo[m], bh0, bh1);   // lo*hi
                    mma8(D[m][n], ahi[m], bl0, bl1);   // hi*lo
                }
            }
        }

        // ---- epilogue: exact reference score formula, running first-min argmin ----
        const int cg0 = ch * BC + c0;
        #pragma unroll
        for (int m = 0; m < 2; m++) {
            #pragma unroll
            for (int rr = 0; rr < 2; rr++) {
                const int slot = m * 2 + rr;
                const float x2 = x2r[slot];
                float v = bv[slot]; int idx = bi[slot];
                #pragma unroll
                for (int n = 0; n < 8; n++) {
                    const int cbase = cg0 + n * 8 + 2 * t4;
                    float2 e2p = *(const float2*)&e2s[cbase];
                    float d0 = D[m][n][rr * 2 + 0];
                    float d1 = D[m][n][rr * 2 + 1];
                    // d2 = fl(fl(x2 - 2*dot) + e2) — replicates reference fp32 formula
                    float s0 = __fadd_rn(__fsub_rn(x2, __fmul_rn(2.0f, d0)), e2p.x);
                    float s1 = __fadd_rn(__fsub_rn(x2, __fmul_rn(2.0f, d1)), e2p.y);
                    if (s0 < v) { v = s0; idx = cbase; }
                    if (s1 < v) { v = s1; idx = cbase + 1; }
                }
                bv[slot] = v; bi[slot] = idx;
            }
        }

        if (ch + 1 < NCHUNK)
            asm volatile("cp.async.wait_group 0;" ::: "memory");
        __syncthreads();
    }

    // Reduce within quad (lanes sharing a pixel row), ties -> lower index.
    #pragma unroll
    for (int s = 0; s < 4; s++) {
        float v = bv[s]; int idx = bi[s];
        #pragma unroll
        for (int off = 1; off < 4; off <<= 1) {
            float ov = __shfl_xor_sync(0xffffffffu, v, off);
            int   oi = __shfl_xor_sync(0xffffffffu, idx, off);
            if (ov < v || (ov == v && oi < idx)) { v = ov; idx = oi; }
        }
        bv[s] = v; bi[s] = idx;
    }
    // Merge the two n-warps per pixel row.
    if (w_n == 0 && t4 == 0) {
        #pragma unroll
        for (int s = 0; s < 4; s++) {
            int row = p0 + (s >> 1) * 16 + (s & 1) * 8 + g;
            bVs[row] = bv[s]; bIs[row] = bi[s];
        }
    }
    __syncthreads();
    if (w_n == 1 && t4 == 0) {
        #pragma unroll
        for (int s = 0; s < 4; s++) {
            int row = p0 + (s >> 1) * 16 + (s & 1) * 8 + g;
            if (bv[s] < bVs[row] || (bv[s] == bVs[row] && bi[s] < bIs[row])) {
                bVs[row] = bv[s]; bIs[row] = bi[s];
            }
        }
    }
    __syncthreads();

    // Gather codebook rows and write channel-first output (coalesced stores).
    float* outbase = out + (size_t)b * D_DIM * 4096 + hw0;
    for (int i = tid; i < D_DIM * BPX; i += TPB) {
        int d = i >> 7, px = i & 127;
        outbase[(size_t)d * 4096 + px] = __ldg(&g_Et[d * K_CODES + bIs[px]]);
    }
}

extern "C" void kernel_launch(void* const* d_in, const int* in_sizes, int n_in,
                              void* d_out, int out_size) {
    const float* lat = (const float*)d_in[0];
    const float* cb  = (const float*)d_in[1];
    float* out = (float*)d_out;
    cudaFuncSetAttribute(vq_main, cudaFuncAttributeMaxDynamicSharedMemorySize, SMEM_DYN);
    prep_kernel<<<128, 256>>>(cb);
    vq_main<<<512, TPB, SMEM_DYN>>>(lat, out);
}

// round 7
// speedup vs baseline: 1.9036x; 1.6430x over previous
#include <cuda_runtime.h>
#include <cstdint>

#define D_DIM   128
#define K_CODES 1024
#define BPX     128            // pixels per block
#define BC      128            // codes per chunk
#define NCHUNK  (K_CODES / BC) // 8
#define TPB     256
#define PSTR    132            // padded row stride (words) -> conflict-free LDS
#define PLANE   (64 * PSTR)    // words per packed plane (64 k-pairs x 132)
#define XWORDS  (2 * PLANE)    // X hi + X lo planes
#define BBUF    (2 * PLANE)    // per-chunk B buffer: hi + lo planes
#define SMEM_DYN ((XWORDS + 2 * BBUF) * 4)   // 202752 B

// Static scratch (no dynamic allocation allowed)
__device__ float    g_Et[D_DIM * K_CODES];       // transposed codebook (output gather)
__device__ float    g_e2[K_CODES];
__device__ unsigned g_B0[NCHUNK * 64 * BC];      // codebook bf16x2 hi plane  [ch][kp][code]
__device__ unsigned g_B1[NCHUNK * 64 * BC];      // codebook bf16x2 residual plane

// pack: element0 (even k) -> low half, element1 (odd k) -> high half
__device__ __forceinline__ unsigned packbf(float lo, float hi) {
    unsigned r; asm("cvt.rn.bf16x2.f32 %0, %1, %2;" : "=r"(r) : "f"(hi), "f"(lo)); return r;
}
__device__ __forceinline__ float lo_f(unsigned p) { return __uint_as_float(p << 16); }
__device__ __forceinline__ float hi_f(unsigned p) { return __uint_as_float(p & 0xFFFF0000u); }
__device__ __forceinline__ void split2(float e0, float e1, unsigned& pH, unsigned& pL) {
    pH = packbf(e0, e1);
    pL = packbf(__fsub_rn(e0, lo_f(pH)), __fsub_rn(e1, hi_f(pH)));
}
__device__ __forceinline__ void mma16(float* d, const unsigned* a, unsigned b0, unsigned b1) {
    asm volatile(
        "mma.sync.aligned.m16n8k16.row.col.f32.bf16.bf16.f32 "
        "{%0,%1,%2,%3}, {%4,%5,%6,%7}, {%8,%9}, {%0,%1,%2,%3};"
        : "+f"(d[0]), "+f"(d[1]), "+f"(d[2]), "+f"(d[3])
        : "r"(a[0]), "r"(a[1]), "r"(a[2]), "r"(a[3]), "r"(b0), "r"(b1));
}
__device__ __forceinline__ void cp16(void* s, const void* g) {
    unsigned sa = (unsigned)__cvta_generic_to_shared(s);
    asm volatile("cp.async.cg.shared.global [%0], [%1], 16;" :: "r"(sa), "l"(g));
}

// prep: transpose codebook, e2, and packed bf16x2 hi/lo planes per chunk.
__global__ void prep_kernel(const float* __restrict__ cb) {
    int i = blockIdx.x * blockDim.x + threadIdx.x;
    int nt = gridDim.x * blockDim.x;
    for (int idx = i; idx < D_DIM * K_CODES; idx += nt) {
        int k = idx >> 7, d = idx & 127;
        g_Et[d * K_CODES + k] = cb[idx];
    }
    for (int idx = i; idx < K_CODES * 64; idx += nt) {   // (code, k-pair)
        int k = idx >> 6, kp = idx & 63;
        float e0 = cb[k * D_DIM + 2 * kp];
        float e1 = cb[k * D_DIM + 2 * kp + 1];
        unsigned pH, pL;
        split2(e0, e1, pH, pL);
        int ch = k >> 7, c = k & 127;
        g_B0[(ch * 64 + kp) * BC + c] = pH;
        g_B1[(ch * 64 + kp) * BC + c] = pL;
    }
    for (int k = i; k < K_CODES; k += nt) {
        const float* row = cb + k * D_DIM;
        float s = 0.f;
        for (int d = 0; d < D_DIM; d++) s = __fadd_rn(s, __fmul_rn(row[d], row[d]));
        g_e2[k] = s;
    }
}

__global__ __launch_bounds__(TPB, 1) void vq_main(const float* __restrict__ lat,
                                                  float* __restrict__ out) {
    extern __shared__ unsigned smem[];
    unsigned* X0p = smem;                  // [kp][px] packed bf16x2 hi
    unsigned* X1p = smem + PLANE;          // residual
    unsigned* Bbase = smem + XWORDS;       // 2 buffers x (hi plane | lo plane)

    __shared__ float x2s[BPX];
    __shared__ float e2s[K_CODES];
    __shared__ float bVs[BPX];
    __shared__ int   bIs[BPX];

    const int tid  = threadIdx.x;
    const int wid  = tid >> 5;
    const int lane = tid & 31;
    const int g    = lane >> 2;      // fragment row/col group
    const int t4   = lane & 3;       // k-pair selector
    const int w_m  = wid >> 1;       // 4 m-warps
    const int w_n  = wid & 1;        // 2 n-warps
    const int p0   = w_m * 32;       // warp pixel base
    const int c0   = w_n * 64;       // warp code base within chunk

    const int gp  = blockIdx.x * BPX;
    const int b   = gp >> 12;
    const int hw0 = gp & 4095;
    const float* latbase = lat + (size_t)b * D_DIM * 4096 + hw0;

    // Issue chunk-0 B-plane loads (async) first.
    for (int i = tid; i < 2 * 64 * 32; i += TPB) {
        int pl = i >> 11, r = (i >> 5) & 63, s = i & 31;
        const unsigned* src = (pl ? g_B1 : g_B0) + (size_t)r * BC + s * 4;
        cp16(&Bbase[pl * PLANE + r * PSTR + s * 4], src);
    }
    asm volatile("cp.async.commit_group;");

    // Convert X once: packed bf16x2 hi/lo planes [kp][px].
    for (int i = tid; i < 64 * BPX; i += TPB) {
        int kp = i >> 7, px = i & 127;
        float xe = latbase[(size_t)(2 * kp) * 4096 + px];
        float xo = latbase[(size_t)(2 * kp + 1) * 4096 + px];
        unsigned pH, pL;
        split2(xe, xo, pH, pL);
        X0p[kp * PSTR + px] = pH;
        X1p[kp * PSTR + px] = pL;
    }
    for (int i = tid; i < K_CODES; i += TPB) e2s[i] = g_e2[i];

    // x2 per pixel (same sequential-d fp32 sum as the certified kernels)
    if (tid < BPX) {
        float s = 0.f;
        for (int d = 0; d < D_DIM; d++) {
            float v = latbase[(size_t)d * 4096 + tid];
            s = __fadd_rn(s, __fmul_rn(v, v));
        }
        x2s[tid] = s;
    }
    asm volatile("cp.async.wait_group 0;" ::: "memory");
    __syncthreads();

    // Per-thread row slots: slot = m*2+rr -> pixel row p0 + m*16 + rr*8 + g
    float x2r[4], bv[4];
    int   bi[4];
    #pragma unroll
    for (int s = 0; s < 4; s++) {
        x2r[s] = x2s[p0 + (s >> 1) * 16 + (s & 1) * 8 + g];
        bv[s] = 3.4e38f; bi[s] = 0;
    }

    for (int ch = 0; ch < NCHUNK; ch++) {
        unsigned* Bb = Bbase + (ch & 1) * BBUF;

        if (ch + 1 < NCHUNK) {   // prefetch next chunk's planes into other buffer
            unsigned* nb = Bbase + ((ch + 1) & 1) * BBUF;
            for (int i = tid; i < 2 * 64 * 32; i += TPB) {
                int pl = i >> 11, r = (i >> 5) & 63, s = i & 31;
                const unsigned* src = (pl ? g_B1 : g_B0) + (size_t)((ch + 1) * 64 + r) * BC + s * 4;
                cp16(&nb[pl * PLANE + r * PSTR + s * 4], src);
            }
            asm volatile("cp.async.commit_group;");
        }

        float D[2][8][4];
        #pragma unroll
        for (int m = 0; m < 2; m++)
            #pragma unroll
            for (int n = 0; n < 8; n++)
                #pragma unroll
                for (int q = 0; q < 4; q++) D[m][n][q] = 0.f;

        #pragma unroll 2
        for (int kb = 0; kb < 8; kb++) {       // 8 k-blocks of 16
            const int r0 = kb * 8 + t4;        // k-pair rows for this thread
            const int r1 = r0 + 4;
            unsigned aH[2][4], aL[2][4], bH[8][2], bL[8][2];
            #pragma unroll
            for (int m = 0; m < 2; m++) {
                const int pxb = p0 + m * 16 + g;
                aH[m][0] = X0p[r0 * PSTR + pxb];
                aH[m][1] = X0p[r0 * PSTR + pxb + 8];
                aH[m][2] = X0p[r1 * PSTR + pxb];
                aH[m][3] = X0p[r1 * PSTR + pxb + 8];
                aL[m][0] = X1p[r0 * PSTR + pxb];
                aL[m][1] = X1p[r0 * PSTR + pxb + 8];
                aL[m][2] = X1p[r1 * PSTR + pxb];
                aL[m][3] = X1p[r1 * PSTR + pxb + 8];
            }
            #pragma unroll
            for (int n = 0; n < 8; n++) {
                const int cc = c0 + n * 8 + g;
                bH[n][0] = Bb[r0 * PSTR + cc];
                bH[n][1] = Bb[r1 * PSTR + cc];
                bL[n][0] = Bb[PLANE + r0 * PSTR + cc];
                bL[n][1] = Bb[PLANE + r1 * PSTR + cc];
            }
            // pass-major: 16 independent accumulator chains per pass
            #pragma unroll
            for (int n = 0; n < 8; n++)
                #pragma unroll
                for (int m = 0; m < 2; m++) mma16(D[m][n], aH[m], bH[n][0], bH[n][1]);
            #pragma unroll
            for (int n = 0; n < 8; n++)
                #pragma unroll
                for (int m = 0; m < 2; m++) mma16(D[m][n], aL[m], bH[n][0], bH[n][1]);
            #pragma unroll
            for (int n = 0; n < 8; n++)
                #pragma unroll
                for (int m = 0; m < 2; m++) mma16(D[m][n], aH[m], bL[n][0], bL[n][1]);
        }

        // ---- epilogue: exact reference score formula, running first-min argmin ----
        const int cg0 = ch * BC + c0;
        #pragma unroll
        for (int m = 0; m < 2; m++) {
            #pragma unroll
            for (int rr = 0; rr < 2; rr++) {
                const int slot = m * 2 + rr;
                const float x2 = x2r[slot];
                float v = bv[slot]; int idx = bi[slot];
                #pragma unroll
                for (int n = 0; n < 8; n++) {
                    const int cbase = cg0 + n * 8 + 2 * t4;
                    float2 e2p = *(const float2*)&e2s[cbase];
                    float d0 = D[m][n][rr * 2 + 0];
                    float d1 = D[m][n][rr * 2 + 1];
                    // d2 = fl(fl(x2 - 2*dot) + e2) — replicates reference fp32 formula
                    float s0 = __fadd_rn(__fsub_rn(x2, __fmul_rn(2.0f, d0)), e2p.x);
                    float s1 = __fadd_rn(__fsub_rn(x2, __fmul_rn(2.0f, d1)), e2p.y);
                    if (s0 < v) { v = s0; idx = cbase; }
                    if (s1 < v) { v = s1; idx = cbase + 1; }
                }
                bv[slot] = v; bi[slot] = idx;
            }
        }

        if (ch + 1 < NCHUNK)
            asm volatile("cp.async.wait_group 0;" ::: "memory");
        __syncthreads();
    }

    // Reduce within quad (lanes sharing a pixel row), ties -> lower index.
    #pragma unroll
    for (int s = 0; s < 4; s++) {
        float v = bv[s]; int idx = bi[s];
        #pragma unroll
        for (int off = 1; off < 4; off <<= 1) {
            float ov = __shfl_xor_sync(0xffffffffu, v, off);
            int   oi = __shfl_xor_sync(0xffffffffu, idx, off);
            if (ov < v || (ov == v && oi < idx)) { v = ov; idx = oi; }
        }
        bv[s] = v; bi[s] = idx;
    }
    // Merge the two n-warps per pixel row.
    if (w_n == 0 && t4 == 0) {
        #pragma unroll
        for (int s = 0; s < 4; s++) {
            int row = p0 + (s >> 1) * 16 + (s & 1) * 8 + g;
            bVs[row] = bv[s]; bIs[row] = bi[s];
        }
    }
    __syncthreads();
    if (w_n == 1 && t4 == 0) {
        #pragma unroll
        for (int s = 0; s < 4; s++) {
            int row = p0 + (s >> 1) * 16 + (s & 1) * 8 + g;
            if (bv[s] < bVs[row] || (bv[s] == bVs[row] && bi[s] < bIs[row])) {
                bVs[row] = bv[s]; bIs[row] = bi[s];
            }
        }
    }
    __syncthreads();

    // Gather codebook rows and write channel-first output (coalesced stores).
    float* outbase = out + (size_t)b * D_DIM * 4096 + hw0;
    for (int i = tid; i < D_DIM * BPX; i += TPB) {
        int d = i >> 7, px = i & 127;
        outbase[(size_t)d * 4096 + px] = __ldg(&g_Et[d * K_CODES + bIs[px]]);
    }
}

extern "C" void kernel_launch(void* const* d_in, const int* in_sizes, int n_in,
                              void* d_out, int out_size) {
    const float* lat = (const float*)d_in[0];
    const float* cb  = (const float*)d_in[1];
    float* out = (float*)d_out;
    cudaFuncSetAttribute(vq_main, cudaFuncAttributeMaxDynamicSharedMemorySize, SMEM_DYN);
    prep_kernel<<<128, 256>>>(cb);
    vq_main<<<512, TPB, SMEM_DYN>>>(lat, out);
}